// round 14
// baseline (speedup 1.0000x reference)
#include <cuda_runtime.h>
#include <cstdint>

#define N_NODES 50000
#define N_EDGES 800000
#define CDIM 128
#define CH 64                            // channel half-width
#define NC (N_NODES * CDIM)
#define E_CAP (N_EDGES + 4 * N_NODES)   // padded edge capacity

typedef unsigned long long u64;

// ---------------- scratch (static device globals; zero-initialized, no allocation) --------
__device__ int    g_cnt[N_NODES];          // always zero at call entry (scan re-zeroes)
__device__ int    g_off[N_NODES + 1];
__device__ int    g_cur[N_NODES];
__device__ float4 g_edge[E_CAP];           // {col-as-bits, vr, vi, 0}; pad slots stay zero
__device__ u64    g_y[NC];                 // interleaved (yr, yi) pairs, [row][channel]

// ---------------- packed f32x2 helpers ----------------
__device__ __forceinline__ u64 pk(float lo, float hi) {
    u64 r; asm("mov.b64 %0, {%1,%2};" : "=l"(r) : "f"(lo), "f"(hi)); return r;
}
__device__ __forceinline__ void upk(u64 v, float& lo, float& hi) {
    asm("mov.b64 {%0,%1}, %2;" : "=f"(lo), "=f"(hi) : "l"(v));
}
__device__ __forceinline__ u64 ffma2(u64 a, u64 b, u64 c) {
    u64 d; asm("fma.rn.f32x2 %0, %1, %2, %3;" : "=l"(d) : "l"(a), "l"(b), "l"(c)); return d;
}

// ---------------- counting sort pipeline (pad-to-4 offsets) ----------------
__global__ void hist_kernel(const int* __restrict__ row) {
    int e = blockIdx.x * blockDim.x + threadIdx.x;
    if (e < N_EDGES) atomicAdd(&g_cnt[row[e]], 1);
}

// single-block coalesced scan: 1024 threads, 49 chunk iterations, shfl block-scan
__global__ __launch_bounds__(1024)
void scan_kernel() {
    __shared__ int wsum[32];
    int t = threadIdx.x, lane = t & 31, wid = t >> 5;
    int run = 0;
    const int ITERS = (N_NODES + 1023) / 1024;  // 49
    for (int it = 0; it < ITERS; it++) {
        int idx = it * 1024 + t;
        int c = (idx < N_NODES) ? g_cnt[idx] : 0;
        int v = (c + 3) & ~3;
        int s = v;
        #pragma unroll
        for (int d = 1; d < 32; d <<= 1) {
            int u = __shfl_up_sync(0xffffffffu, s, d);
            if (lane >= d) s += u;
        }
        if (lane == 31) wsum[wid] = s;
        __syncthreads();
        if (wid == 0) {
            int ws = wsum[lane];
            #pragma unroll
            for (int d = 1; d < 32; d <<= 1) {
                int u = __shfl_up_sync(0xffffffffu, ws, d);
                if (lane >= d) ws += u;
            }
            wsum[lane] = ws;
        }
        __syncthreads();
        int base = (wid > 0) ? wsum[wid - 1] : 0;
        int excl = run + base + s - v;
        if (idx < N_NODES) {
            g_off[idx] = excl;
            g_cur[idx] = excl;
            g_cnt[idx] = 0;          // restore invariant for next call
        }
        run += wsum[31];
        __syncthreads();             // protect wsum before next iteration
    }
    if (t == 0) g_off[N_NODES] = run;
}

__global__ void scatter_kernel(const int* __restrict__ row, const int* __restrict__ col,
                               const float* __restrict__ lr, const float* __restrict__ li) {
    int e = blockIdx.x * blockDim.x + threadIdx.x;
    if (e < N_EDGES) {
        int r = row[e];
        int p = atomicAdd(&g_cur[r], 1);
        g_edge[p] = make_float4(__int_as_float(col[e]), lr[e], li[e], 0.0f);
    }
}

// ---------------- GEMM half: Y[:, co..co+64) = X @ W[:, co..co+64), interleaved pairs ----
// W-half staged once (32KB); A prefetched one tile ahead in registers (R12 pipeline).
// 64KB smem -> 3 blocks/SM. Lane owns channels co+2l, co+2l+1.
#define GM_TPB    256
#define GM_WPB    8
#define GM_RPW    4
#define GM_ROWS   (GM_WPB * GM_RPW)                      // 32 rows / tile
#define GM_TILES  ((N_NODES + GM_ROWS - 1) / GM_ROWS)    // 1563
#define GM_GRID   (148 * 3)                              // 444 = one wave @ 3 blk/SM
#define GM_SMEM   (CDIM * CH * 4 + GM_ROWS * CDIM * 8)   // 32KB Wt + 32KB At = 65536

#define LOAD_A_REGS(TILE) do {                                                  \
    int rb_ = (TILE) * GM_ROWS + warp * GM_RPW;                                 \
    _Pragma("unroll")                                                           \
    for (int rr = 0; rr < GM_RPW; rr++) {                                       \
        int row_ = min(rb_ + rr, N_NODES - 1);                                  \
        pr[rr][0] = *(const float2*)(Xr + row_ * CDIM + 2 * lane);              \
        pi[rr][0] = *(const float2*)(Xi + row_ * CDIM + 2 * lane);              \
        pr[rr][1] = *(const float2*)(Xr + row_ * CDIM + 64 + 2 * lane);         \
        pi[rr][1] = *(const float2*)(Xi + row_ * CDIM + 64 + 2 * lane);         \
    }                                                                           \
} while (0)

__global__ __launch_bounds__(GM_TPB, 3)
void gemm_half(const float* __restrict__ Xr, const float* __restrict__ Xi,
               const float* __restrict__ W, u64* __restrict__ Y, int co) {
    extern __shared__ char smraw[];
    float* Wt = (float*)smraw;                        // [128][64], staged once
    u64*   At = (u64*)(smraw + CDIM * CH * 4);        // [32 rows][128] (xr,xi) pairs

    int tid  = threadIdx.x;
    int warp = tid >> 5;
    int lane = tid & 31;

    // stage W half once: Wt[k][c] = W[k][co + c]  (float4 per thread x8)
    {
        #pragma unroll
        for (int i = 0; i < CDIM * CH / 4 / GM_TPB; i++) {
            int v = i * GM_TPB + tid;
            int k = v >> 4, c4 = v & 15;
            ((float4*)Wt)[v] = *(const float4*)(W + k * CDIM + co + c4 * 4);
        }
    }

    // prologue: prefetch first tile's A into registers
    float2 pr[GM_RPW][2], pi[GM_RPW][2];
    LOAD_A_REGS(blockIdx.x);
    __syncthreads();   // W ready

    for (int tile = blockIdx.x; tile < GM_TILES; tile += GM_GRID) {
        int rbase = tile * GM_ROWS + warp * GM_RPW;

        // STS prefetched A (register-sourced)
        #pragma unroll
        for (int rr = 0; rr < GM_RPW; rr++) {
            #pragma unroll
            for (int seg = 0; seg < 2; seg++) {
                ulonglong2 v;
                v.x = pk(pr[rr][seg].x, pi[rr][seg].x);
                v.y = pk(pr[rr][seg].y, pi[rr][seg].y);
                *(ulonglong2*)&At[(warp * GM_RPW + rr) * CDIM + seg * 64 + 2 * lane] = v;
            }
        }
        __syncthreads();

        // prefetch NEXT tile's A now; latency hides under this tile's compute
        int nt = tile + GM_GRID;
        if (nt < GM_TILES) LOAD_A_REGS(nt);

        u64 acc[GM_RPW][2];
        #pragma unroll
        for (int rr = 0; rr < GM_RPW; rr++) { acc[rr][0] = 0ull; acc[rr][1] = 0ull; }

        const u64* Aw = At + warp * GM_RPW * CDIM;
        #pragma unroll 8
        for (int kk = 0; kk < CDIM; kk += 2) {
            float2 wA = *(const float2*)&Wt[kk * CH + 2 * lane];        // W[k][2 cols]
            float2 wB = *(const float2*)&Wt[(kk + 1) * CH + 2 * lane];  // W[k+1][2 cols]
            u64 wa0 = pk(wA.x, wA.x), wa1 = pk(wA.y, wA.y);
            u64 wb0 = pk(wB.x, wB.x), wb1 = pk(wB.y, wB.y);
            #pragma unroll
            for (int rr = 0; rr < GM_RPW; rr++) {
                ulonglong2 a = *(const ulonglong2*)&Aw[rr * CDIM + kk];  // (xr,xi) k, k+1
                acc[rr][0] = ffma2(a.x, wa0, acc[rr][0]);
                acc[rr][1] = ffma2(a.x, wa1, acc[rr][1]);
                acc[rr][0] = ffma2(a.y, wb0, acc[rr][0]);
                acc[rr][1] = ffma2(a.y, wb1, acc[rr][1]);
            }
        }

        // store interleaved pairs directly (no unpack)
        #pragma unroll
        for (int rr = 0; rr < GM_RPW; rr++) {
            int row = rbase + rr;
            if (row < N_NODES) {
                ulonglong2 v; v.x = acc[rr][0]; v.y = acc[rr][1];
                *(ulonglong2*)&Y[row * CDIM + co + 2 * lane] = v;
            }
        }
        __syncthreads();
    }
}

// ---------------- SpMM half: out[:, co..co+64) = L_complex @ Y_half + X_half -------------
#define S_TPB 256
#define S_WPB 8
#define S_BLOCKS (148 * 3)   // 444 = one full wave at 3 blocks/SM

// pair math: acV1 += (vr,vr)*y ; acV2 += (vi,vi)*y
// final: ar = acV1.lo - acV2.hi ; ai = acV2.lo + acV1.hi
#define SB(MD, YP, J) do {                                                     \
    u64 vr2 = pk(MD.y, MD.y), vi2 = pk(MD.z, MD.z);                            \
    acV1[0] = ffma2(vr2, YP.x, acV1[0]);                                       \
    acV1[1] = ffma2(vr2, YP.y, acV1[1]);                                       \
    acV2[0] = ffma2(vi2, YP.x, acV2[0]);                                       \
    acV2[1] = ffma2(vi2, YP.y, acV2[1]);                                       \
    int jn = (J) + 4;                                                          \
    if (jn < cnt) {                                                            \
        MD = mrow[jn];                                                         \
        int c = __float_as_int(MD.x);                                          \
        YP = *(const ulonglong2*)(YL + (c << 7));                              \
    }                                                                          \
} while (0)

__global__ __launch_bounds__(S_TPB)
void spmm_half(const float* __restrict__ Xr, const float* __restrict__ Xi,
               const u64* __restrict__ Y, const float4* __restrict__ edge,
               float* __restrict__ out, int co) {
    __shared__ float4 meta[S_WPB][32];

    int warp = threadIdx.x >> 5;
    int lane = threadIdx.x & 31;
    float4* mrow = meta[warp];
    const u64* YL = Y + co + 2 * lane;   // lane owns pair-channels co+2l, co+2l+1
    float* outR = out;
    float* outI = out + NC;

    int gw = blockIdx.x * S_WPB + warp;
    int nw = gridDim.x * S_WPB;

    for (int row = gw; row < N_NODES; row += nw) {
        int e0  = g_off[row];
        int deg = g_off[row + 1] - e0;   // multiple of 4 (pad slots are zero edges)
        u64 acV1[2] = {0ull, 0ull}, acV2[2] = {0ull, 0ull};

        for (int base = 0; base < deg; base += 32) {
            int cnt = min(32, deg - base);   // multiple of 4, >= 4
            if (lane < cnt) mrow[lane] = edge[e0 + base + lane];   // one LDG.128
            __syncwarp();

            float4 md0 = mrow[0], md1 = mrow[1], md2 = mrow[2], md3 = mrow[3];
            ulonglong2 y0, y1, y2, y3;
            {
                int c0 = __float_as_int(md0.x), c1 = __float_as_int(md1.x);
                int c2 = __float_as_int(md2.x), c3 = __float_as_int(md3.x);
                y0 = *(const ulonglong2*)(YL + (c0 << 7));
                y1 = *(const ulonglong2*)(YL + (c1 << 7));
                y2 = *(const ulonglong2*)(YL + (c2 << 7));
                y3 = *(const ulonglong2*)(YL + (c3 << 7));
            }
            for (int j = 0; j < cnt; j += 4) {
                SB(md0, y0, j);
                SB(md1, y1, j + 1);
                SB(md2, y2, j + 2);
                SB(md3, y3, j + 3);
            }
            __syncwarp();   // protect meta before next chunk restages
        }

        // epilogue: combine pair-accumulators, add residual, store half channels
        float s1l0, s1h0, s1l1, s1h1, s2l0, s2h0, s2l1, s2h1;
        upk(acV1[0], s1l0, s1h0); upk(acV1[1], s1l1, s1h1);
        upk(acV2[0], s2l0, s2h0); upk(acV2[1], s2l1, s2h1);
        float ar0 = s1l0 - s2h0, ai0 = s2l0 + s1h0;
        float ar1 = s1l1 - s2h1, ai1 = s2l1 + s1h1;
        float2 rxr = *(const float2*)(Xr + row * CDIM + co + 2 * lane);
        float2 rxi = *(const float2*)(Xi + row * CDIM + co + 2 * lane);
        *(float2*)(outR + row * CDIM + co + 2 * lane) =
            make_float2(ar0 + rxr.x, ar1 + rxr.y);
        *(float2*)(outI + row * CDIM + co + 2 * lane) =
            make_float2(ai0 + rxi.x, ai1 + rxi.y);
    }
}

// ---------------- launch: channel-split pipeline across two streams ----------------------
// t0: gemm1 (s2) || prep (main);  t1: spmm1 (main) || gemm2 (s2);  t2: spmm2 (main)
extern "C" void kernel_launch(void* const* d_in, const int* in_sizes, int n_in,
                              void* d_out, int out_size) {
    const float* Xr = (const float*)d_in[0];
    const float* Xi = (const float*)d_in[1];
    const float* Lr = (const float*)d_in[2];
    const float* Li = (const float*)d_in[3];
    const float* W  = (const float*)d_in[4];
    const int*   row = (const int*)d_in[5];
    const int*   col = (const int*)d_in[6];
    float* out = (float*)d_out;

    // resolve scratch symbol addresses so kernels get true __restrict__ params
    void *y_p = nullptr, *edge_p = nullptr;
    cudaGetSymbolAddress(&y_p, g_y);
    cudaGetSymbolAddress(&edge_p, g_edge);
    u64* Y = (u64*)y_p;
    const float4* edge = (const float4*)edge_p;

    cudaFuncSetAttribute(gemm_half, cudaFuncAttributeMaxDynamicSharedMemorySize, GM_SMEM);

    cudaStream_t s2 = nullptr;
    cudaEvent_t evFork = nullptr, evG1 = nullptr, evG2 = nullptr;
    bool forked =
        (cudaStreamCreateWithFlags(&s2, cudaStreamNonBlocking) == cudaSuccess) &&
        (cudaEventCreateWithFlags(&evFork, cudaEventDisableTiming) == cudaSuccess) &&
        (cudaEventCreateWithFlags(&evG1, cudaEventDisableTiming) == cudaSuccess) &&
        (cudaEventCreateWithFlags(&evG2, cudaEventDisableTiming) == cudaSuccess);

    if (forked) {
        cudaEventRecord(evFork, 0);
        cudaStreamWaitEvent(s2, evFork, 0);

        // main chain: edge preprocessing (runs concurrent with gemm1)
        hist_kernel<<<(N_EDGES + 255) / 256, 256>>>(row);
        scan_kernel<<<1, 1024>>>();
        scatter_kernel<<<(N_EDGES + 255) / 256, 256>>>(row, col, Lr, Li);

        // side chain: the two gemm halves
        gemm_half<<<GM_GRID, GM_TPB, GM_SMEM, s2>>>(Xr, Xi, W, Y, 0);
        cudaEventRecord(evG1, s2);
        gemm_half<<<GM_GRID, GM_TPB, GM_SMEM, s2>>>(Xr, Xi, W, Y, CH);
        cudaEventRecord(evG2, s2);

        // spmm1 needs scatter (stream order) + gemm1; runs concurrent with gemm2
        cudaStreamWaitEvent(0, evG1, 0);
        spmm_half<<<S_BLOCKS, S_TPB>>>(Xr, Xi, Y, edge, out, 0);
        cudaStreamWaitEvent(0, evG2, 0);
        spmm_half<<<S_BLOCKS, S_TPB>>>(Xr, Xi, Y, edge, out, CH);
    } else {
        // fallback: serialized (identical semantics)
        hist_kernel<<<(N_EDGES + 255) / 256, 256>>>(row);
        scan_kernel<<<1, 1024>>>();
        scatter_kernel<<<(N_EDGES + 255) / 256, 256>>>(row, col, Lr, Li);
        gemm_half<<<GM_GRID, GM_TPB, GM_SMEM>>>(Xr, Xi, W, Y, 0);
        gemm_half<<<GM_GRID, GM_TPB, GM_SMEM>>>(Xr, Xi, W, Y, CH);
        spmm_half<<<S_BLOCKS, S_TPB>>>(Xr, Xi, Y, edge, out, 0);
        spmm_half<<<S_BLOCKS, S_TPB>>>(Xr, Xi, Y, edge, out, CH);
    }
    // note: s2/events intentionally not destroyed while referenced by the captured
    // graph; kernel_launch runs only a handful of times, so the leak is bounded.
}

// round 15
// speedup vs baseline: 1.1320x; 1.1320x over previous
#include <cuda_runtime.h>
#include <cuda_fp16.h>
#include <cstdint>

#define N_NODES 50000
#define N_EDGES 800000
#define CDIM 128
#define NC (N_NODES * CDIM)
#define E_CAP (N_EDGES + 4 * N_NODES)   // padded edge capacity

typedef unsigned long long u64;

// ---------------- scratch (static device globals; zero-initialized, no allocation) --------
__device__ int      g_cnt[N_NODES];        // always zero at call entry (scan re-zeroes)
__device__ int      g_off[N_NODES + 1];
__device__ int      g_cur[N_NODES];
__device__ float4   g_edge[E_CAP];         // {col-as-bits, vr, vi, 0}; pad slots stay zero
__device__ uint32_t g_yh[NC];              // half2(yr, yi) per (row, channel)

// ---------------- packed f32x2 helpers ----------------
__device__ __forceinline__ u64 pk(float lo, float hi) {
    u64 r; asm("mov.b64 %0, {%1,%2};" : "=l"(r) : "f"(lo), "f"(hi)); return r;
}
__device__ __forceinline__ void upk(u64 v, float& lo, float& hi) {
    asm("mov.b64 {%0,%1}, %2;" : "=f"(lo), "=f"(hi) : "l"(v));
}
__device__ __forceinline__ u64 ffma2(u64 a, u64 b, u64 c) {
    u64 d; asm("fma.rn.f32x2 %0, %1, %2, %3;" : "=l"(d) : "l"(a), "l"(b), "l"(c)); return d;
}
__device__ __forceinline__ uint32_t f2h2(float lo, float hi) {
    __half2 h = __floats2half2_rn(lo, hi);
    return *(uint32_t*)&h;
}

// ---------------- counting sort pipeline (pad-to-4 offsets) ----------------
__global__ void hist_kernel(const int* __restrict__ row) {
    int e = blockIdx.x * blockDim.x + threadIdx.x;
    if (e < N_EDGES) atomicAdd(&g_cnt[row[e]], 1);
}

// single-block coalesced scan: 1024 threads, 49 chunk iterations, shfl block-scan
__global__ __launch_bounds__(1024)
void scan_kernel() {
    __shared__ int wsum[32];
    int t = threadIdx.x, lane = t & 31, wid = t >> 5;
    int run = 0;
    const int ITERS = (N_NODES + 1023) / 1024;  // 49
    for (int it = 0; it < ITERS; it++) {
        int idx = it * 1024 + t;
        int c = (idx < N_NODES) ? g_cnt[idx] : 0;
        int v = (c + 3) & ~3;
        int s = v;
        #pragma unroll
        for (int d = 1; d < 32; d <<= 1) {
            int u = __shfl_up_sync(0xffffffffu, s, d);
            if (lane >= d) s += u;
        }
        if (lane == 31) wsum[wid] = s;
        __syncthreads();
        if (wid == 0) {
            int ws = wsum[lane];
            #pragma unroll
            for (int d = 1; d < 32; d <<= 1) {
                int u = __shfl_up_sync(0xffffffffu, ws, d);
                if (lane >= d) ws += u;
            }
            wsum[lane] = ws;
        }
        __syncthreads();
        int base = (wid > 0) ? wsum[wid - 1] : 0;
        int excl = run + base + s - v;
        if (idx < N_NODES) {
            g_off[idx] = excl;
            g_cur[idx] = excl;
            g_cnt[idx] = 0;          // restore invariant for next call
        }
        run += wsum[31];
        __syncthreads();             // protect wsum before next iteration
    }
    if (t == 0) g_off[N_NODES] = run;
}

__global__ void scatter_kernel(const int* __restrict__ row, const int* __restrict__ col,
                               const float* __restrict__ lr, const float* __restrict__ li) {
    int e = blockIdx.x * blockDim.x + threadIdx.x;
    if (e < N_EDGES) {
        int r = row[e];
        int p = atomicAdd(&g_cur[r], 1);
        g_edge[p] = make_float4(__int_as_float(col[e]), lr[e], li[e], 0.0f);
    }
}

// ---------------- GEMM kernel: Yh = half2(X @ W pairs), complex-pair packed --------------
// R12 structure: W staged once (64KB), A prefetched one tile ahead in registers.
#define GM_TPB    256
#define GM_WPB    8
#define GM_RPW    4
#define GM_ROWS   (GM_WPB * GM_RPW)                      // 32 rows / tile
#define GM_TILES  ((N_NODES + GM_ROWS - 1) / GM_ROWS)    // 1563
#define GM_GRID   (148 * 2)                              // 296 = one full wave @ 2 blk/SM
#define GM_SMEM   (CDIM * CDIM * 4 + GM_ROWS * CDIM * 8) // 64KB W + 32KB A = 98304

#define LOAD_A_REGS(TILE) do {                                                  \
    int rb_ = (TILE) * GM_ROWS + warp * GM_RPW;                                 \
    _Pragma("unroll")                                                           \
    for (int rr = 0; rr < GM_RPW; rr++) {                                       \
        int row_ = min(rb_ + rr, N_NODES - 1);                                  \
        pr[rr][0] = *(const float2*)(Xr + row_ * CDIM + 2 * lane);              \
        pi[rr][0] = *(const float2*)(Xi + row_ * CDIM + 2 * lane);              \
        pr[rr][1] = *(const float2*)(Xr + row_ * CDIM + 64 + 2 * lane);         \
        pi[rr][1] = *(const float2*)(Xi + row_ * CDIM + 64 + 2 * lane);         \
    }                                                                           \
} while (0)

__global__ __launch_bounds__(GM_TPB, 2)
void gemm_kernel(const float* __restrict__ Xr, const float* __restrict__ Xi,
                 const float* __restrict__ W, uint32_t* __restrict__ Yh) {
    extern __shared__ char smraw[];
    float* Wt = (float*)smraw;                        // [128][128], staged once
    u64*   At = (u64*)(smraw + CDIM * CDIM * 4);      // [32 rows][128] (xr,xi) pairs

    int tid  = threadIdx.x;
    int warp = tid >> 5;
    int lane = tid & 31;

    // stage full W once (coalesced float4; 16 per thread)
    {
        const float4* s4 = (const float4*)W;
        float4* d4 = (float4*)Wt;
        #pragma unroll
        for (int i = 0; i < CDIM * CDIM / 4 / GM_TPB; i++)
            d4[i * GM_TPB + tid] = s4[i * GM_TPB + tid];
    }

    // prologue: prefetch first tile's A into registers
    float2 pr[GM_RPW][2], pi[GM_RPW][2];
    LOAD_A_REGS(blockIdx.x);
    __syncthreads();   // W ready

    for (int tile = blockIdx.x; tile < GM_TILES; tile += GM_GRID) {
        int rbase = tile * GM_ROWS + warp * GM_RPW;

        // STS prefetched A (register-sourced, no global latency at this barrier)
        #pragma unroll
        for (int rr = 0; rr < GM_RPW; rr++) {
            #pragma unroll
            for (int seg = 0; seg < 2; seg++) {
                ulonglong2 v;
                v.x = pk(pr[rr][seg].x, pi[rr][seg].x);
                v.y = pk(pr[rr][seg].y, pi[rr][seg].y);
                *(ulonglong2*)&At[(warp * GM_RPW + rr) * CDIM + seg * 64 + 2 * lane] = v;
            }
        }
        __syncthreads();

        // prefetch NEXT tile's A now; latency hides under this tile's compute
        int nt = tile + GM_GRID;
        if (nt < GM_TILES) LOAD_A_REGS(nt);

        u64 acc[GM_RPW][4];
        #pragma unroll
        for (int rr = 0; rr < GM_RPW; rr++)
            #pragma unroll
            for (int c = 0; c < 4; c++) acc[rr][c] = 0ull;

        const u64* Aw = At + warp * GM_RPW * CDIM;
        #pragma unroll 8
        for (int kk = 0; kk < CDIM; kk += 2) {
            float4 w4a = *(const float4*)&Wt[kk * CDIM + 4 * lane];
            float4 w4b = *(const float4*)&Wt[(kk + 1) * CDIM + 4 * lane];
            u64 wa0 = pk(w4a.x, w4a.x), wa1 = pk(w4a.y, w4a.y);
            u64 wa2 = pk(w4a.z, w4a.z), wa3 = pk(w4a.w, w4a.w);
            u64 wb0 = pk(w4b.x, w4b.x), wb1 = pk(w4b.y, w4b.y);
            u64 wb2 = pk(w4b.z, w4b.z), wb3 = pk(w4b.w, w4b.w);
            #pragma unroll
            for (int rr = 0; rr < GM_RPW; rr++) {
                ulonglong2 a = *(const ulonglong2*)&Aw[rr * CDIM + kk];
                acc[rr][0] = ffma2(a.x, wa0, acc[rr][0]);
                acc[rr][1] = ffma2(a.x, wa1, acc[rr][1]);
                acc[rr][2] = ffma2(a.x, wa2, acc[rr][2]);
                acc[rr][3] = ffma2(a.x, wa3, acc[rr][3]);
                acc[rr][0] = ffma2(a.y, wb0, acc[rr][0]);
                acc[rr][1] = ffma2(a.y, wb1, acc[rr][1]);
                acc[rr][2] = ffma2(a.y, wb2, acc[rr][2]);
                acc[rr][3] = ffma2(a.y, wb3, acc[rr][3]);
            }
        }

        // write Y as half2(yr,yi) per channel (one uint4 = lane's 4 channels)
        #pragma unroll
        for (int rr = 0; rr < GM_RPW; rr++) {
            int row = rbase + rr;
            if (row < N_NODES) {
                float lo, hi;
                uint4 o;
                upk(acc[rr][0], lo, hi); o.x = f2h2(lo, hi);
                upk(acc[rr][1], lo, hi); o.y = f2h2(lo, hi);
                upk(acc[rr][2], lo, hi); o.z = f2h2(lo, hi);
                upk(acc[rr][3], lo, hi); o.w = f2h2(lo, hi);
                *(uint4*)&Yh[row * CDIM + 4 * lane] = o;
            }
        }
        __syncthreads();
    }
}

// ---------------- SpMM kernel: out = L_complex @ Y + X  (half Y gather, fp32 accum) ------
#define S_TPB 256
#define S_WPB 8
#define S_BLOCKS (148 * 3)   // 444 = one full wave at 3 blocks/SM

// pair math per channel c: acV1[c] += (vr,vr)*(yr,yi) ; acV2[c] += (vi,vi)*(yr,yi)
// final: ar = acV1.lo - acV2.hi ; ai = acV2.lo + acV1.hi
#define SB(MD, Y4, J) do {                                                     \
    u64 vr2 = pk(MD.y, MD.y), vi2 = pk(MD.z, MD.z);                            \
    float2 f0 = __half22float2(*(__half2*)&Y4.x);                              \
    float2 f1 = __half22float2(*(__half2*)&Y4.y);                              \
    float2 f2 = __half22float2(*(__half2*)&Y4.z);                              \
    float2 f3 = __half22float2(*(__half2*)&Y4.w);                              \
    u64 p0 = pk(f0.x, f0.y), p1 = pk(f1.x, f1.y);                              \
    u64 p2 = pk(f2.x, f2.y), p3 = pk(f3.x, f3.y);                              \
    acV1[0] = ffma2(vr2, p0, acV1[0]); acV2[0] = ffma2(vi2, p0, acV2[0]);      \
    acV1[1] = ffma2(vr2, p1, acV1[1]); acV2[1] = ffma2(vi2, p1, acV2[1]);      \
    acV1[2] = ffma2(vr2, p2, acV1[2]); acV2[2] = ffma2(vi2, p2, acV2[2]);      \
    acV1[3] = ffma2(vr2, p3, acV1[3]); acV2[3] = ffma2(vi2, p3, acV2[3]);      \
    int jn = (J) + 4;                                                          \
    if (jn < cnt) {                                                            \
        MD = mrow[jn];                                                         \
        int c = __float_as_int(MD.x);                                          \
        Y4 = *(const uint4*)(YL + (c << 7));                                   \
    }                                                                          \
} while (0)

__global__ __launch_bounds__(S_TPB)
void spmm_kernel(const float* __restrict__ Xr, const float* __restrict__ Xi,
                 const uint32_t* __restrict__ Yh, const float4* __restrict__ edge,
                 float* __restrict__ out) {
    __shared__ float4 meta[S_WPB][32];

    int warp = threadIdx.x >> 5;
    int lane = threadIdx.x & 31;
    float4* mrow = meta[warp];
    const uint32_t* YL = Yh + 4 * lane;   // lane owns channels 4l..4l+3 (half2 pairs)
    float* outR = out;
    float* outI = out + NC;

    int gw = blockIdx.x * S_WPB + warp;
    int nw = gridDim.x * S_WPB;

    for (int row = gw; row < N_NODES; row += nw) {
        int e0  = g_off[row];
        int deg = g_off[row + 1] - e0;   // multiple of 4 (pad slots are zero edges)
        u64 acV1[4] = {0ull, 0ull, 0ull, 0ull};
        u64 acV2[4] = {0ull, 0ull, 0ull, 0ull};

        for (int base = 0; base < deg; base += 32) {
            int cnt = min(32, deg - base);   // multiple of 4, >= 4
            if (lane < cnt) mrow[lane] = edge[e0 + base + lane];   // one LDG.128
            __syncwarp();

            float4 md0 = mrow[0], md1 = mrow[1], md2 = mrow[2], md3 = mrow[3];
            uint4 y0, y1, y2, y3;
            {
                int c0 = __float_as_int(md0.x), c1 = __float_as_int(md1.x);
                int c2 = __float_as_int(md2.x), c3 = __float_as_int(md3.x);
                y0 = *(const uint4*)(YL + (c0 << 7));
                y1 = *(const uint4*)(YL + (c1 << 7));
                y2 = *(const uint4*)(YL + (c2 << 7));
                y3 = *(const uint4*)(YL + (c3 << 7));
            }
            for (int j = 0; j < cnt; j += 4) {
                SB(md0, y0, j);
                SB(md1, y1, j + 1);
                SB(md2, y2, j + 2);
                SB(md3, y3, j + 3);
            }
            __syncwarp();   // protect meta before next chunk restages
        }

        // epilogue: combine pair-accumulators, add residual X, store
        float r[4], im[4];
        #pragma unroll
        for (int c = 0; c < 4; c++) {
            float s1l, s1h, s2l, s2h;
            upk(acV1[c], s1l, s1h);
            upk(acV2[c], s2l, s2h);
            r[c]  = s1l - s2h;
            im[c] = s2l + s1h;
        }
        float4 rxr = *(const float4*)(Xr + row * CDIM + 4 * lane);
        float4 rxi = *(const float4*)(Xi + row * CDIM + 4 * lane);
        *(float4*)(outR + row * CDIM + 4 * lane) =
            make_float4(r[0] + rxr.x, r[1] + rxr.y, r[2] + rxr.z, r[3] + rxr.w);
        *(float4*)(outI + row * CDIM + 4 * lane) =
            make_float4(im[0] + rxi.x, im[1] + rxi.y, im[2] + rxi.z, im[3] + rxi.w);
    }
}

// ---------------- launch: fork gemm onto a side stream (concurrent graph branches) -------
extern "C" void kernel_launch(void* const* d_in, const int* in_sizes, int n_in,
                              void* d_out, int out_size) {
    const float* Xr = (const float*)d_in[0];
    const float* Xi = (const float*)d_in[1];
    const float* Lr = (const float*)d_in[2];
    const float* Li = (const float*)d_in[3];
    const float* W  = (const float*)d_in[4];
    const int*   row = (const int*)d_in[5];
    const int*   col = (const int*)d_in[6];
    float* out = (float*)d_out;

    // resolve scratch symbol addresses so kernels get true __restrict__ params
    void *yh_p = nullptr, *edge_p = nullptr;
    cudaGetSymbolAddress(&yh_p, g_yh);
    cudaGetSymbolAddress(&edge_p, g_edge);
    uint32_t* Yh = (uint32_t*)yh_p;
    const float4* edge = (const float4*)edge_p;

    cudaFuncSetAttribute(gemm_kernel, cudaFuncAttributeMaxDynamicSharedMemorySize, GM_SMEM);

    cudaStream_t s2 = nullptr;
    cudaEvent_t evFork = nullptr, evGemm = nullptr;
    bool forked =
        (cudaStreamCreateWithFlags(&s2, cudaStreamNonBlocking) == cudaSuccess) &&
        (cudaEventCreateWithFlags(&evFork, cudaEventDisableTiming) == cudaSuccess) &&
        (cudaEventCreateWithFlags(&evGemm, cudaEventDisableTiming) == cudaSuccess);

    if (forked) {
        // fork: side stream inherits capture via event wait
        cudaEventRecord(evFork, 0);
        cudaStreamWaitEvent(s2, evFork, 0);
        gemm_kernel<<<GM_GRID, GM_TPB, GM_SMEM, s2>>>(Xr, Xi, W, Yh);
        cudaEventRecord(evGemm, s2);

        // main chain (edge preprocessing), concurrent with gemm
        hist_kernel<<<(N_EDGES + 255) / 256, 256>>>(row);
        scan_kernel<<<1, 1024>>>();
        scatter_kernel<<<(N_EDGES + 255) / 256, 256>>>(row, col, Lr, Li);

        // join, then spmm consumes both
        cudaStreamWaitEvent(0, evGemm, 0);
        spmm_kernel<<<S_BLOCKS, S_TPB>>>(Xr, Xi, Yh, edge, out);
    } else {
        // fallback: serialized (identical semantics)
        hist_kernel<<<(N_EDGES + 255) / 256, 256>>>(row);
        scan_kernel<<<1, 1024>>>();
        scatter_kernel<<<(N_EDGES + 255) / 256, 256>>>(row, col, Lr, Li);
        gemm_kernel<<<GM_GRID, GM_TPB, GM_SMEM>>>(Xr, Xi, W, Yh);
        spmm_kernel<<<S_BLOCKS, S_TPB>>>(Xr, Xi, Yh, edge, out);
    }
    // note: s2/evFork/evGemm intentionally not destroyed while referenced by the
    // captured graph; kernel_launch runs only a handful of times, so the leak is bounded.
}